// round 6
// baseline (speedup 1.0000x reference)
#include <cuda_runtime.h>

#define LSEQ 768
#define NSEQ 256
#define MD   256
#define MSAD 23
#define SEQD 22
#define ZD   128
#define NB   14
#define RC   32
#define QSTRIDE 96    // floats per pair in dup-quad smem: 23k * 4 + pad

// Scratch: kb[i,:] = seq@Wk + bk + bpos  (384 KB)
__device__ float g_kb[LSEQ * ZD];

// ---- packed f32x2 helpers (sm_103a, PTX-only) ----
typedef unsigned long long ull;
__device__ __forceinline__ ull pk2(float a, float b) {
    ull r; asm("mov.b64 %0, {%1, %2};" : "=l"(r) : "f"(a), "f"(b)); return r;
}
__device__ __forceinline__ ull fma2(ull a, ull b, ull c) {
    ull d; asm("fma.rn.f32x2 %0, %1, %2, %3;" : "=l"(d) : "l"(a), "l"(b), "l"(c));
    return d;
}
__device__ __forceinline__ void st1cs(float* p, ull a) {
    asm volatile("st.global.cs.b64 [%0], %1;" :: "l"(p), "l"(a) : "memory");
}
__device__ __forceinline__ float4 ld4(const float* p) {
    return *reinterpret_cast<const float4*>(p);
}

// ---------------------------------------------------------------------------
// kb precompute: 2 rows per 256-thread block.
// ---------------------------------------------------------------------------
__global__ __launch_bounds__(256) void kbkern(
    const float* __restrict__ seq, const float* __restrict__ Wk,
    const float* __restrict__ bk,  const float* __restrict__ bpos)
{
    const int tid = threadIdx.x;
    const int rr  = tid >> 7;
    const int c   = tid & 127;
    const int i   = blockIdx.x * 2 + rr;

    __shared__ float s[2][SEQD];
    if (tid < 2 * SEQD)
        s[tid / SEQD][tid % SEQD] = seq[(blockIdx.x * 2 + tid / SEQD) * SEQD + tid % SEQD];
    __syncthreads();

    float a = bk[c] + bpos[c];
    #pragma unroll
    for (int d = 0; d < SEQD; d++) a += s[rr][d] * Wk[d * ZD + c];
    g_kb[i * ZD + c] = a;
}

// ---------------------------------------------------------------------------
// Fused main kernel: 1920 blocks x 128 threads.
//   b % 5 in {0..3} -> m-path block (1536: l x row-half)
//   b % 5 == 4      -> z-path block (384: 4 j's x i-half)
// ---------------------------------------------------------------------------
__global__ __launch_bounds__(128, 6) void mainkern(
    const float* __restrict__ seq,  const float* __restrict__ msa,
    const float* __restrict__ Wmsa, const float* __restrict__ bmsa,
    const float* __restrict__ Ws,   const float* __restrict__ bs,
    const float* __restrict__ Wq,   const float* __restrict__ bq,
    const float* __restrict__ Wpos, const float* __restrict__ Wpos2,
    const float* __restrict__ bpos2,
    float* __restrict__ outm, float* __restrict__ outz)
{
    const int b   = blockIdx.x;
    const int tid = threadIdx.x;
    const int sel = b % 5;

    if (sel == 4) {
        // ------------- z-path: z[i,j,:] = sq[j] + kb[i] + Wpos[rel] ---------
        const int zid   = b / 5;
        const int j     = (zid >> 1) * 4 + (tid >> 5);
        const int c     = (tid & 31) * 4;

        float4 q;
        q.x = bq[c]; q.y = bq[c + 1]; q.z = bq[c + 2]; q.w = bq[c + 3];
        #pragma unroll
        for (int d = 0; d < SEQD; d++) {
            const float  sv = seq[j * SEQD + d];
            const float4 w  = ld4(Wq + d * ZD + c);
            q.x += sv * w.x; q.y += sv * w.y; q.z += sv * w.z; q.w += sv * w.w;
        }

        const int i0 = (zid & 1) * (LSEQ / 2);
        for (int ib = i0; ib < i0 + LSEQ / 2; ib += 8) {
            float4 kbv[8];
            #pragma unroll
            for (int u = 0; u < 8; u++)
                kbv[u] = __ldg(reinterpret_cast<const float4*>(&g_kb[(ib + u) * ZD + c]));
            #pragma unroll
            for (int u = 0; u < 8; u++) {
                const int i = ib + u;
                int rel = j - i;
                rel = min(max(rel, -RC), RC) + RC;
                const float4 wp = ld4(Wpos + rel * ZD + c);
                float4 o;
                o.x = q.x + kbv[u].x + wp.x;
                o.y = q.y + kbv[u].y + wp.y;
                o.z = q.z + kbv[u].z + wp.z;
                o.w = q.w + kbv[u].w + wp.w;
                __stcs(reinterpret_cast<float4*>(&outz[((long)i * LSEQ + j) * ZD + c]), o);
            }
        }
        return;
    }

    // ------------ m-path: m[n,l,:] = msa[n,l,:]@Wmsa + sp[l,:] --------------
    // 2 channels/thread (low regs), 128 rows/block, dup-quad smem layout.
    const int mid = (b / 5) * 4 + sel;    // 0..1535
    const int l   = mid >> 1;
    const int n0  = (mid & 1) * 128;      // row-half base
    const int c   = tid * 2;              // channel pair 0..254

    // dupq[p][k] = {m[2p,k], m[2p,k], m[2p+1,k], m[2p+1,k]}
    __shared__ float dupq[64 * QSTRIDE];  // 24.6 KB
    __shared__ float srow[SEQD];

    if (tid < SEQD) srow[tid] = seq[l * SEQD + tid];
    for (int idx = tid; idx < 128 * MSAD; idx += 128) {
        const int n = idx / MSAD;
        const int k = idx - n * MSAD;
        const float v = msa[((n0 + n) * LSEQ + l) * MSAD + k];
        *reinterpret_cast<float2*>(&dupq[(n >> 1) * QSTRIDE + 4 * k + 2 * (n & 1)])
            = make_float2(v, v);
    }
    __syncthreads();

    // per-thread weights: one packed f32x2 per k (46 regs)
    ull w[MSAD];
    #pragma unroll
    for (int k = 0; k < MSAD; k++) {
        const float2 wv = *reinterpret_cast<const float2*>(&Wmsa[k * MD + c]);
        w[k] = pk2(wv.x, wv.y);
    }

    // sp[l, c..c+1]
    float spx = bs[c]     + bpos2[c]     + bmsa[c];
    float spy = bs[c + 1] + bpos2[c + 1] + bmsa[c + 1];
    #pragma unroll
    for (int d = 0; d < SEQD; d++) {
        const float  sv = srow[d];
        const float2 wv = *reinterpret_cast<const float2*>(&Ws[d * MD + c]);
        spx += sv * wv.x; spy += sv * wv.y;
    }
    #pragma unroll
    for (int bb = 0; bb < NB; bb++)
        if ((l >> bb) & 1) {
            const float2 wv = *reinterpret_cast<const float2*>(&Wpos2[bb * MD + c]);
            spx += wv.x; spy += wv.y;
        }
    const ull sp01 = pk2(spx, spy);

    // main loop: one row-pair per iter, 23 LDS.128 + 46 fma2, zero movs
    const long stride = (long)LSEQ * MD;
    float* obase = &outm[((long)n0 * LSEQ + l) * MD + c];
    for (int p = 0; p < 64; p++) {
        const float* base = &dupq[p * QSTRIDE];
        ull accA = sp01, accB = sp01;
        #pragma unroll
        for (int k = 0; k < MSAD; k++) {
            const ulonglong2 d = *reinterpret_cast<const ulonglong2*>(base + 4 * k);
            accA = fma2(w[k], d.x, accA);   // row 2p
            accB = fma2(w[k], d.y, accB);   // row 2p+1
        }
        float* o = obase + (long)(2 * p) * stride;
        st1cs(o,          accA);
        st1cs(o + stride, accB);
    }
}

// ---------------------------------------------------------------------------
extern "C" void kernel_launch(void* const* d_in, const int* in_sizes, int n_in,
                              void* d_out, int out_size)
{
    const float* seq   = (const float*)d_in[0];
    const float* msa   = (const float*)d_in[1];
    const float* Wmsa  = (const float*)d_in[2];
    const float* bmsa  = (const float*)d_in[3];
    const float* Ws    = (const float*)d_in[4];
    const float* bs    = (const float*)d_in[5];
    const float* Wq    = (const float*)d_in[6];
    const float* bq    = (const float*)d_in[7];
    const float* Wk    = (const float*)d_in[8];
    const float* bk    = (const float*)d_in[9];
    const float* Wpos  = (const float*)d_in[10];
    const float* bpos  = (const float*)d_in[11];
    const float* Wpos2 = (const float*)d_in[12];
    const float* bpos2 = (const float*)d_in[13];

    float* outm = (float*)d_out;
    float* outz = outm + (long)NSEQ * LSEQ * MD;

    kbkern<<<LSEQ / 2, 256>>>(seq, Wk, bk, bpos);
    mainkern<<<1920, 128>>>(seq, msa, Wmsa, bmsa, Ws, bs, Wq, bq,
                            Wpos, Wpos2, bpos2, outm, outz);
}

// round 7
// speedup vs baseline: 1.3618x; 1.3618x over previous
#include <cuda_runtime.h>

#define LSEQ 768
#define NSEQ 256
#define MD   256
#define MSAD 23
#define SEQD 22
#define ZD   128
#define NB   14
#define RC   32
#define PSTRIDE 48    // floats per row-pair in smem: 23 k * 2 + pad

// Scratch: kb[i,:] = seq@Wk + bk + bpos  (384 KB)
__device__ float g_kb[LSEQ * ZD];

// ---- packed f32x2 helpers (sm_103a, PTX-only) ----
typedef unsigned long long ull;
__device__ __forceinline__ ull pk2(float a, float b) {
    ull r; asm("mov.b64 %0, {%1, %2};" : "=l"(r) : "f"(a), "f"(b)); return r;
}
__device__ __forceinline__ ull dup2(float a) {
    ull r; asm("mov.b64 %0, {%1, %1};" : "=l"(r) : "f"(a)); return r;
}
__device__ __forceinline__ void upk2(ull v, float& a, float& b) {
    asm("mov.b64 {%0, %1}, %2;" : "=f"(a), "=f"(b) : "l"(v));
}
__device__ __forceinline__ ull fma2(ull a, ull b, ull c) {
    ull d; asm("fma.rn.f32x2 %0, %1, %2, %3;" : "=l"(d) : "l"(a), "l"(b), "l"(c));
    return d;
}
__device__ __forceinline__ ull add2(ull a, ull b) {
    ull d; asm("add.rn.f32x2 %0, %1, %2;" : "=l"(d) : "l"(a), "l"(b)); return d;
}
__device__ __forceinline__ void st2cs(float* p, ull a, ull b) {
    asm volatile("st.global.cs.v2.u64 [%0], {%1, %2};" :: "l"(p), "l"(a), "l"(b) : "memory");
}
__device__ __forceinline__ float4 ld4(const float* p) {
    return *reinterpret_cast<const float4*>(p);
}
__device__ __forceinline__ unsigned smem_u32(const void* p) {
    unsigned a;
    asm("{ .reg .u64 t; cvta.to.shared.u64 t, %1; cvt.u32.u64 %0, t; }" : "=r"(a) : "l"(p));
    return a;
}
__device__ __forceinline__ void cpasync4(unsigned dst, const float* src) {
    asm volatile("cp.async.ca.shared.global [%0], [%1], 4;" :: "r"(dst), "l"(src));
}

// ---------------------------------------------------------------------------
// kb precompute: 2 rows per 256-thread block.
// ---------------------------------------------------------------------------
__global__ __launch_bounds__(256) void kbkern(
    const float* __restrict__ seq, const float* __restrict__ Wk,
    const float* __restrict__ bk,  const float* __restrict__ bpos)
{
    const int tid = threadIdx.x;
    const int rr  = tid >> 7;
    const int c   = tid & 127;
    const int i   = blockIdx.x * 2 + rr;

    __shared__ float s[2][SEQD];
    if (tid < 2 * SEQD)
        s[tid / SEQD][tid % SEQD] = seq[(blockIdx.x * 2 + tid / SEQD) * SEQD + tid % SEQD];
    __syncthreads();

    float a = bk[c] + bpos[c];
    #pragma unroll
    for (int d = 0; d < SEQD; d++) a += s[rr][d] * Wk[d * ZD + c];
    g_kb[i * ZD + c] = a;
}

// ---------------------------------------------------------------------------
// Fused main kernel: 1536 blocks x 128 threads, strict 1:1 interleave.
//   b & 1 == 0 -> m-path (l = b>>1, all 256 rows)
//   b & 1 == 1 -> z-path (4 j's, quarter of the i range)
// ---------------------------------------------------------------------------
__global__ __launch_bounds__(128, 4) void mainkern(
    const float* __restrict__ seq,  const float* __restrict__ msa,
    const float* __restrict__ Wmsa, const float* __restrict__ bmsa,
    const float* __restrict__ Ws,   const float* __restrict__ bs,
    const float* __restrict__ Wq,   const float* __restrict__ bq,
    const float* __restrict__ Wpos, const float* __restrict__ Wpos2,
    const float* __restrict__ bpos2,
    float* __restrict__ outm, float* __restrict__ outz)
{
    const int b   = blockIdx.x;
    const int tid = threadIdx.x;

    if (b & 1) {
        // ------------- z-path: z[i,j,:] = sq[j] + kb[i] + Wpos[rel] ---------
        const int zid = b >> 1;           // 0..767
        const int j   = (zid >> 2) * 4 + (tid >> 5);
        const int iq  = zid & 3;          // i-quarter
        const int c   = (tid & 31) * 4;

        float4 q;
        q.x = bq[c]; q.y = bq[c + 1]; q.z = bq[c + 2]; q.w = bq[c + 3];
        #pragma unroll
        for (int d = 0; d < SEQD; d++) {
            const float  sv = seq[j * SEQD + d];
            const float4 w  = ld4(Wq + d * ZD + c);
            q.x += sv * w.x; q.y += sv * w.y; q.z += sv * w.z; q.w += sv * w.w;
        }
        const ull q01 = pk2(q.x, q.y);
        const ull q23 = pk2(q.z, q.w);

        const int i0 = iq * (LSEQ / 4);
        for (int ib = i0; ib < i0 + LSEQ / 4; ib += 8) {
            // batch 8 independent kb loads (MLP=8 over L2 latency)
            ulonglong2 kbv[8];
            #pragma unroll
            for (int u = 0; u < 8; u++)
                kbv[u] = *reinterpret_cast<const ulonglong2*>(&g_kb[(ib + u) * ZD + c]);
            #pragma unroll
            for (int u = 0; u < 8; u++) {
                const int i = ib + u;
                int rel = j - i;
                rel = min(max(rel, -RC), RC) + RC;
                const ulonglong2 wp = *reinterpret_cast<const ulonglong2*>(&Wpos[rel * ZD + c]);
                const ull o01 = add2(add2(q01, kbv[u].x), wp.x);
                const ull o23 = add2(add2(q23, kbv[u].y), wp.y);
                st2cs(&outz[((long)i * LSEQ + j) * ZD + c], o01, o23);
            }
        }
        return;
    }

    // ------------ m-path: m[n,l,:] = msa[n,l,:]@Wmsa + sp[l,:] --------------
    const int l  = b >> 1;                // 0..767
    const int rg = tid >> 6;              // 0..1
    const int c  = (tid & 63) * 4;

    // Row-PAIR interleaved layout: pairs[p][k][s] = msa[2p+s, l, k]
    __shared__ float pairs[(NSEQ / 2) * PSTRIDE];   // 24.6 KB
    __shared__ float srow[SEQD];

    if (tid < SEQD) srow[tid] = seq[l * SEQD + tid];
    // cp.async fill: 46 outstanding 4B copies per thread, no reg round-trip
    for (int idx = tid; idx < NSEQ * MSAD; idx += 128) {
        const int n = idx / MSAD;
        const int k = idx - n * MSAD;
        const unsigned dst = smem_u32(&pairs[(n >> 1) * PSTRIDE + 2 * k + (n & 1)]);
        cpasync4(dst, &msa[(n * LSEQ + l) * MSAD + k]);
    }
    asm volatile("cp.async.commit_group;" ::: "memory");

    // per-thread weights, channel-packed f32x2 (92 regs) — overlaps cp.async
    ull w0[MSAD], w1[MSAD];
    #pragma unroll
    for (int k = 0; k < MSAD; k++) {
        const float4 w = ld4(Wmsa + k * MD + c);
        w0[k] = pk2(w.x, w.y);
        w1[k] = pk2(w.z, w.w);
    }

    // sp[l, c..c+3]
    float4 sp;
    sp.x = bs[c]     + bpos2[c]     + bmsa[c];
    sp.y = bs[c + 1] + bpos2[c + 1] + bmsa[c + 1];
    sp.z = bs[c + 2] + bpos2[c + 2] + bmsa[c + 2];
    sp.w = bs[c + 3] + bpos2[c + 3] + bmsa[c + 3];
    #pragma unroll
    for (int bb = 0; bb < NB; bb++)
        if ((l >> bb) & 1) {
            const float4 w = ld4(Wpos2 + bb * MD + c);
            sp.x += w.x; sp.y += w.y; sp.z += w.z; sp.w += w.w;
        }
    asm volatile("cp.async.wait_group 0;" ::: "memory");
    __syncthreads();
    #pragma unroll
    for (int d = 0; d < SEQD; d++) {
        const float  sv = srow[d];
        const float4 w  = ld4(Ws + d * MD + c);
        sp.x += sv * w.x; sp.y += sv * w.y; sp.z += sv * w.z; sp.w += sv * w.w;
    }
    const ull sp01 = pk2(sp.x, sp.y);
    const ull sp23 = pk2(sp.z, sp.w);

    // main loop: one row-PAIR per iteration -> 4 independent fma2 chains,
    // 23 LDS.64 per pair.
    for (int it = 0; it < NSEQ / 4; it++) {
        const int p  = it * 2 + rg;       // pair index 0..127
        const int na = p * 2;             // rows na, na+1
        const float* base = &pairs[p * PSTRIDE];

        ull a01 = sp01, a23 = sp23;       // row na
        ull b01 = sp01, b23 = sp23;       // row na+1
        #pragma unroll
        for (int k = 0; k < MSAD; k++) {
            const float2 v = *reinterpret_cast<const float2*>(base + 2 * k);  // LDS.64
            const ull pa = dup2(v.x);
            const ull pb = dup2(v.y);
            a01 = fma2(w0[k], pa, a01);
            a23 = fma2(w1[k], pa, a23);
            b01 = fma2(w0[k], pb, b01);
            b23 = fma2(w1[k], pb, b23);
        }
        st2cs(&outm[((long)na * LSEQ + l) * MD + c], a01, a23);
        st2cs(&outm[((long)(na + 1) * LSEQ + l) * MD + c], b01, b23);
    }
}

// ---------------------------------------------------------------------------
extern "C" void kernel_launch(void* const* d_in, const int* in_sizes, int n_in,
                              void* d_out, int out_size)
{
    const float* seq   = (const float*)d_in[0];
    const float* msa   = (const float*)d_in[1];
    const float* Wmsa  = (const float*)d_in[2];
    const float* bmsa  = (const float*)d_in[3];
    const float* Ws    = (const float*)d_in[4];
    const float* bs    = (const float*)d_in[5];
    const float* Wq    = (const float*)d_in[6];
    const float* bq    = (const float*)d_in[7];
    const float* Wk    = (const float*)d_in[8];
    const float* bk    = (const float*)d_in[9];
    const float* Wpos  = (const float*)d_in[10];
    const float* bpos  = (const float*)d_in[11];
    const float* Wpos2 = (const float*)d_in[12];
    const float* bpos2 = (const float*)d_in[13];

    float* outm = (float*)d_out;
    float* outz = outm + (long)NSEQ * LSEQ * MD;

    kbkern<<<LSEQ / 2, 256>>>(seq, Wk, bk, bpos);
    mainkern<<<1536, 128>>>(seq, msa, Wmsa, bmsa, Ws, bs, Wq, bq,
                            Wpos, Wpos2, bpos2, outm, outz);
}